// round 4
// baseline (speedup 1.0000x reference)
#include <cuda_runtime.h>
#include <cstdint>

// out[idx] = (Pid[idx] > 0) ? 1.f : 0.f, replicated into both output halves.
// 4x float4 per thread, loads batched front (MLP), streaming ld/st hints.
__global__ void binarize_dup_kernel(const float4* __restrict__ pid,
                                    float4* __restrict__ out,
                                    long long n4, long long half4, int ncopies) {
    long long i0 = ((long long)blockIdx.x * blockDim.x + threadIdx.x) * 4;
    if (i0 + 3 < n4) {
        float4 p0 = __ldcs(pid + i0 + 0);
        float4 p1 = __ldcs(pid + i0 + 1);
        float4 p2 = __ldcs(pid + i0 + 2);
        float4 p3 = __ldcs(pid + i0 + 3);
        float4 v0, v1, v2, v3;
        v0.x = p0.x > 0.f ? 1.f : 0.f; v0.y = p0.y > 0.f ? 1.f : 0.f;
        v0.z = p0.z > 0.f ? 1.f : 0.f; v0.w = p0.w > 0.f ? 1.f : 0.f;
        v1.x = p1.x > 0.f ? 1.f : 0.f; v1.y = p1.y > 0.f ? 1.f : 0.f;
        v1.z = p1.z > 0.f ? 1.f : 0.f; v1.w = p1.w > 0.f ? 1.f : 0.f;
        v2.x = p2.x > 0.f ? 1.f : 0.f; v2.y = p2.y > 0.f ? 1.f : 0.f;
        v2.z = p2.z > 0.f ? 1.f : 0.f; v2.w = p2.w > 0.f ? 1.f : 0.f;
        v3.x = p3.x > 0.f ? 1.f : 0.f; v3.y = p3.y > 0.f ? 1.f : 0.f;
        v3.z = p3.z > 0.f ? 1.f : 0.f; v3.w = p3.w > 0.f ? 1.f : 0.f;
        __stcs(out + i0 + 0, v0);
        __stcs(out + i0 + 1, v1);
        __stcs(out + i0 + 2, v2);
        __stcs(out + i0 + 3, v3);
        if (ncopies > 1) {
            __stcs(out + half4 + i0 + 0, v0);
            __stcs(out + half4 + i0 + 1, v1);
            __stcs(out + half4 + i0 + 2, v2);
            __stcs(out + half4 + i0 + 3, v3);
        }
    } else {
        for (long long i = i0; i < n4; i++) {
            float4 p = __ldcs(pid + i);
            float4 v;
            v.x = p.x > 0.f ? 1.f : 0.f; v.y = p.y > 0.f ? 1.f : 0.f;
            v.z = p.z > 0.f ? 1.f : 0.f; v.w = p.w > 0.f ? 1.f : 0.f;
            __stcs(out + i, v);
            if (ncopies > 1) __stcs(out + half4 + i, v);
        }
    }
}

// One warp per batch. Predicates read ORIGINAL Pid (reference computes them
// pre-edit); the 8 edited cells are pairwise distinct when valid, so write
// order is irrelevant. Lanes fan out the scattered stores.
__global__ void fixup_kernel(const float* __restrict__ pid,
                             const int* __restrict__ inter,
                             float* __restrict__ out,
                             int B, int V, long long half, int ncopies) {
    int b = blockIdx.x;
    if (b >= B) return;
    int lane = threadIdx.x;

    int e10 = inter[b * 4 + 0];
    int e11 = inter[b * 4 + 1];
    int e20 = inter[b * 4 + 2];
    int e21 = inter[b * 4 + 3];

    bool distinct = (e10 != e11) && (e10 != e20) && (e10 != e21) &&
                    (e11 != e20) && (e11 != e21) && (e20 != e21);
    if (!distinct) return;

    long long base = (long long)b * V * V;
    bool blocked = (pid[base + (long long)e10 * V + e20] > 0.f) ||
                   (pid[base + (long long)e11 * V + e21] > 0.f);
    if (blocked) return;

    float old_pid = (pid[base + (long long)e10 * V + e11] > 0.f) ? 1.f : 0.f;

    // 8 distinct (r,c,val) triples, one per lane, per copy.
    int rs[8] = {e10, e11, e20, e21, e10, e20, e11, e21};
    int cs[8] = {e11, e10, e21, e20, e20, e10, e21, e11};
    float vals[8] = {0.f, 0.f, 0.f, 0.f, old_pid, old_pid, 1.f, 1.f};

    int total = 8 * ncopies;
    if (lane < total) {
        int c = lane / 8;     // copy index
        int k = lane % 8;
        out[base + (long long)c * half + (long long)rs[k] * V + cs[k]] = vals[k];
    }
}

extern "C" void kernel_launch(void* const* d_in, const int* in_sizes, int n_in,
                              void* d_out, int out_size) {
    const float* pid  = (const float*)d_in[0];   // (B, V, V) float32
    const int* inter  = (const int*)d_in[1];     // (B, 2, 2) int32
    float* out = (float*)d_out;

    const int V = 512;
    long long N = (long long)in_sizes[0];          // B*V*V
    int B = (int)(N / ((long long)V * V));         // 256
    int ncopies = (int)((long long)out_size / N);  // 2
    if (ncopies < 1) ncopies = 1;
    if (ncopies > 2) ncopies = 2;

    long long n4 = N / 4;                          // float4 count
    int threads = 256;
    long long perBlock = (long long)threads * 4;   // 4 float4 per thread
    long long blocks = (n4 + perBlock - 1) / perBlock;

    binarize_dup_kernel<<<(unsigned)blocks, threads>>>(
        (const float4*)pid, (float4*)out, n4, N / 4, ncopies);

    fixup_kernel<<<B, 32>>>(pid, inter, out, B, V, N, ncopies);
}

// round 5
// speedup vs baseline: 1.2091x; 1.2091x over previous
#include <cuda_runtime.h>
#include <cstdint>

// out[idx] = (Pid[idx] > 0) ? 1.f : 0.f, replicated into both output halves.
// 1 float4 per thread, fully coalesced, default cache policy (measured best:
// blocked multi-float4 per thread + __stcs regressed 117 -> 144 us).
__global__ void binarize_dup_kernel(const float4* __restrict__ pid,
                                    float4* __restrict__ out,
                                    long long n4, long long half4, int ncopies) {
    long long i = (long long)blockIdx.x * blockDim.x + threadIdx.x;
    if (i >= n4) return;
    float4 p = pid[i];
    float4 v;
    v.x = p.x > 0.f ? 1.f : 0.f;
    v.y = p.y > 0.f ? 1.f : 0.f;
    v.z = p.z > 0.f ? 1.f : 0.f;
    v.w = p.w > 0.f ? 1.f : 0.f;
    out[i] = v;
    if (ncopies > 1) out[i + half4] = v;
}

// One warp per batch. Predicates read ORIGINAL Pid (reference computes them
// all pre-edit); the 8 edited cells are pairwise distinct when valid, so
// write order is irrelevant. Lanes fan out the scattered stores.
__global__ void fixup_kernel(const float* __restrict__ pid,
                             const int* __restrict__ inter,
                             float* __restrict__ out,
                             int B, int V, long long half, int ncopies) {
    int b = blockIdx.x;
    if (b >= B) return;
    int lane = threadIdx.x;

    int e10 = inter[b * 4 + 0];
    int e11 = inter[b * 4 + 1];
    int e20 = inter[b * 4 + 2];
    int e21 = inter[b * 4 + 3];

    bool distinct = (e10 != e11) && (e10 != e20) && (e10 != e21) &&
                    (e11 != e20) && (e11 != e21) && (e20 != e21);
    if (!distinct) return;

    long long base = (long long)b * V * V;
    bool blocked = (pid[base + (long long)e10 * V + e20] > 0.f) ||
                   (pid[base + (long long)e11 * V + e21] > 0.f);
    if (blocked) return;

    float old_pid = (pid[base + (long long)e10 * V + e11] > 0.f) ? 1.f : 0.f;

    // 8 distinct (r,c,val) triples, one per lane, per copy.
    int rs[8] = {e10, e11, e20, e21, e10, e20, e11, e21};
    int cs[8] = {e11, e10, e21, e20, e20, e10, e21, e11};
    float vals[8] = {0.f, 0.f, 0.f, 0.f, old_pid, old_pid, 1.f, 1.f};

    int total = 8 * ncopies;
    if (lane < total) {
        int c = lane / 8;     // copy index
        int k = lane % 8;
        out[base + (long long)c * half + (long long)rs[k] * V + cs[k]] = vals[k];
    }
}

extern "C" void kernel_launch(void* const* d_in, const int* in_sizes, int n_in,
                              void* d_out, int out_size) {
    const float* pid  = (const float*)d_in[0];   // (B, V, V) float32
    const int* inter  = (const int*)d_in[1];     // (B, 2, 2) int32
    float* out = (float*)d_out;

    const int V = 512;
    long long N = (long long)in_sizes[0];          // B*V*V
    int B = (int)(N / ((long long)V * V));         // 256
    int ncopies = (int)((long long)out_size / N);  // 2
    if (ncopies < 1) ncopies = 1;
    if (ncopies > 2) ncopies = 2;

    long long n4 = N / 4;
    int threads = 256;
    long long blocks = (n4 + threads - 1) / threads;

    binarize_dup_kernel<<<(unsigned)blocks, threads>>>(
        (const float4*)pid, (float4*)out, n4, N / 4, ncopies);

    fixup_kernel<<<B, 32>>>(pid, inter, out, B, V, N, ncopies);
}

// round 6
// speedup vs baseline: 1.2369x; 1.0230x over previous
#include <cuda_runtime.h>
#include <cstdint>

// Fused binarize + fixup.
// out[b,r,c] = (Pid[b,r,c] > 0) ? 1 : 0, replicated into both output halves,
// with the reference's 8-cell per-batch edit applied inline.
// All edit predicates depend only on the ORIGINAL Pid (reference computes them
// pre-edit), and the 8 edited cells are pairwise distinct when valid, so each
// thread can patch its own cells independently before storing.
//
// Grid layout: 256 blocks per batch (V*V/4/256 = 65536/256), 256 threads,
// 1 float4 per thread => identical fully-coalesced stream to the measured-best
// binarize kernel (~6.5 TB/s).
__global__ void binarize_fused_kernel(const float4* __restrict__ pid4,
                                      const float* __restrict__ pid,
                                      const int* __restrict__ inter,
                                      float4* __restrict__ out,
                                      long long half4, int ncopies) {
    int bb = blockIdx.x;
    int batch = bb >> 8;                          // 256 blocks per batch
    int inb = ((bb & 255) << 8) | threadIdx.x;    // float4 index within batch [0,65536)
    long long i = ((long long)batch << 16) + inb;

    float4 p = pid4[i];
    float4 v;
    v.x = p.x > 0.f ? 1.f : 0.f;
    v.y = p.y > 0.f ? 1.f : 0.f;
    v.z = p.z > 0.f ? 1.f : 0.f;
    v.w = p.w > 0.f ? 1.f : 0.f;

    // Per-batch edit decision (uniform per block; same-address loads broadcast).
    int e10 = __ldg(inter + batch * 4 + 0);
    int e11 = __ldg(inter + batch * 4 + 1);
    int e20 = __ldg(inter + batch * 4 + 2);
    int e21 = __ldg(inter + batch * 4 + 3);

    bool distinct = (e10 != e11) && (e10 != e20) && (e10 != e21) &&
                    (e11 != e20) && (e11 != e21) && (e20 != e21);
    if (distinct) {
        long long base = (long long)batch << 18;  // * V*V (512*512)
        bool blocked = (__ldg(pid + base + e10 * 512 + e20) > 0.f) ||
                       (__ldg(pid + base + e11 * 512 + e21) > 0.f);
        if (!blocked) {
            float oldp = (__ldg(pid + base + e10 * 512 + e11) > 0.f) ? 1.f : 0.f;
            int r  = inb >> 7;          // row within batch (128 float4 per row)
            int c0 = (inb & 127) << 2;  // first column of this float4

            // 8 edits: (row, col, val)
            int   rr[8] = {e10, e11, e20, e21, e10, e20, e11, e21};
            int   cc[8] = {e11, e10, e21, e20, e20, e10, e21, e11};
            float vv[8] = {0.f, 0.f, 0.f, 0.f, oldp, oldp, 1.f, 1.f};
            #pragma unroll
            for (int k = 0; k < 8; k++) {
                if (r == rr[k]) {
                    int d = cc[k] - c0;
                    if (d == 0) v.x = vv[k];
                    else if (d == 1) v.y = vv[k];
                    else if (d == 2) v.z = vv[k];
                    else if (d == 3) v.w = vv[k];
                }
            }
        }
    }

    out[i] = v;
    if (ncopies > 1) out[i + half4] = v;
}

extern "C" void kernel_launch(void* const* d_in, const int* in_sizes, int n_in,
                              void* d_out, int out_size) {
    const float* pid  = (const float*)d_in[0];   // (B, V, V) float32, V=512
    const int* inter  = (const int*)d_in[1];     // (B, 2, 2) int32
    float* out = (float*)d_out;

    const int V = 512;
    long long N = (long long)in_sizes[0];          // B*V*V
    int B = (int)(N / ((long long)V * V));         // 256
    int ncopies = (int)((long long)out_size / N);  // 2
    if (ncopies < 1) ncopies = 1;
    if (ncopies > 2) ncopies = 2;

    // 256 blocks per batch, 256 threads each, 1 float4 per thread.
    unsigned blocks = (unsigned)B * 256u;
    binarize_fused_kernel<<<blocks, 256>>>(
        (const float4*)pid, pid, inter, (float4*)out, N / 4, ncopies);
}

// round 9
// speedup vs baseline: 1.2385x; 1.0013x over previous
#include <cuda_runtime.h>
#include <cstdint>

// Fused binarize + fixup, 2 float4 per thread in coalesced stride layout:
// thread t of block handles batch-local float4 indices inb0 and inb0+256,
// where consecutive lanes hit consecutive addresses (full 128B-line
// coalescing per LDG.128, unlike the blocked layout that regressed in R2).
// Loads batched before stores to double per-warp MLP.
//
// All edit predicates depend only on the ORIGINAL Pid (the reference computes
// them pre-edit), and the 8 edited cells are pairwise distinct when valid, so
// each thread patches its own cells independently before storing.
__device__ __forceinline__ void apply_fix(float4& v, int inb, bool doFix,
                                          const int* rr, const int* cc,
                                          const float* vv) {
    if (!doFix) return;
    int r  = inb >> 7;          // row within batch (128 float4 per 512-col row)
    int c0 = (inb & 127) << 2;  // first column of this float4
    #pragma unroll
    for (int k = 0; k < 8; k++) {
        if (r == rr[k]) {
            int d = cc[k] - c0;
            if (d == 0) v.x = vv[k];
            else if (d == 1) v.y = vv[k];
            else if (d == 2) v.z = vv[k];
            else if (d == 3) v.w = vv[k];
        }
    }
}

__global__ __launch_bounds__(256)
void binarize_fused_kernel(const float4* __restrict__ pid4,
                           const float* __restrict__ pid,
                           const int* __restrict__ inter,
                           float4* __restrict__ out,
                           long long half4, int ncopies) {
    int bb = blockIdx.x;
    int batch = bb >> 7;                           // 128 blocks per batch
    int inb0 = ((bb & 127) << 9) | threadIdx.x;    // first float4 idx in batch
    int inb1 = inb0 + 256;                         // second (coalesced stride)
    long long base4 = (long long)batch << 16;      // batch * 65536 float4s
    long long i0 = base4 + inb0;
    long long i1 = base4 + inb1;

    // Batch both loads up front (MLP=2 per thread).
    float4 p0 = pid4[i0];
    float4 p1 = pid4[i1];

    float4 v0, v1;
    v0.x = p0.x > 0.f ? 1.f : 0.f; v0.y = p0.y > 0.f ? 1.f : 0.f;
    v0.z = p0.z > 0.f ? 1.f : 0.f; v0.w = p0.w > 0.f ? 1.f : 0.f;
    v1.x = p1.x > 0.f ? 1.f : 0.f; v1.y = p1.y > 0.f ? 1.f : 0.f;
    v1.z = p1.z > 0.f ? 1.f : 0.f; v1.w = p1.w > 0.f ? 1.f : 0.f;

    // Per-batch edit decision (uniform per block; same-address loads broadcast).
    int e10 = __ldg(inter + batch * 4 + 0);
    int e11 = __ldg(inter + batch * 4 + 1);
    int e20 = __ldg(inter + batch * 4 + 2);
    int e21 = __ldg(inter + batch * 4 + 3);

    bool distinct = (e10 != e11) && (e10 != e20) && (e10 != e21) &&
                    (e11 != e20) && (e11 != e21) && (e20 != e21);
    bool doFix = false;
    float oldp = 0.f;
    if (distinct) {
        long long base = (long long)batch << 18;   // batch * 512*512
        bool blocked = (__ldg(pid + base + e10 * 512 + e20) > 0.f) ||
                       (__ldg(pid + base + e11 * 512 + e21) > 0.f);
        if (!blocked) {
            doFix = true;
            oldp = (__ldg(pid + base + e10 * 512 + e11) > 0.f) ? 1.f : 0.f;
        }
    }

    int   rr[8] = {e10, e11, e20, e21, e10, e20, e11, e21};
    int   cc[8] = {e11, e10, e21, e20, e20, e10, e21, e11};
    float vv[8] = {0.f, 0.f, 0.f, 0.f, oldp, oldp, 1.f, 1.f};
    apply_fix(v0, inb0, doFix, rr, cc, vv);
    apply_fix(v1, inb1, doFix, rr, cc, vv);

    out[i0] = v0;
    out[i1] = v1;
    if (ncopies > 1) {
        out[i0 + half4] = v0;
        out[i1 + half4] = v1;
    }
}

extern "C" void kernel_launch(void* const* d_in, const int* in_sizes, int n_in,
                              void* d_out, int out_size) {
    const float* pid  = (const float*)d_in[0];   // (B, V, V) float32, V=512
    const int* inter  = (const int*)d_in[1];     // (B, 2, 2) int32
    float* out = (float*)d_out;

    const int V = 512;
    long long N = (long long)in_sizes[0];          // B*V*V
    int B = (int)(N / ((long long)V * V));         // 256
    int ncopies = (int)((long long)out_size / N);  // 2
    if (ncopies < 1) ncopies = 1;
    if (ncopies > 2) ncopies = 2;

    // 128 blocks per batch, 256 threads, 2 float4 per thread.
    unsigned blocks = (unsigned)B * 128u;
    binarize_fused_kernel<<<blocks, 256>>>(
        (const float4*)pid, pid, inter, (float4*)out, N / 4, ncopies);
}